// round 8
// baseline (speedup 1.0000x reference)
#include <cuda_runtime.h>

// StrictOrthogonal via CholeskyQR1, persistent kernel, 2 CTAs per SM.
// 256 CTAs x 256 threads (occ 2: n_conc=296 >= 256 -> all wave-1 resident,
// grid barrier safe). Per-CTA 64x32 complex chunk resident in SMEM.
// A read once, Out written once. 2 grid barriers. Partials stored
// TRANSPOSED (g_part[elem][cta]) so reduce is coalesced LDG.128.
// R8 fix: chunk is 1024 float4 (not 512) — stage/copy-out do 4 iterations.

#define M_ROWS 16384
#define R_COLS 32
#define CHUNK  64
#define NCTA   256
#define TPB    256

__device__ float    g_part[2048 * NCTA];   // transposed partials (2 MB)
__device__ float2   g_S[R_COLS * R_COLS];  // reduced Gram
__device__ unsigned g_bar[2];              // barrier counters (memset per launch)

// ---------------------------------------------------------------------------
__device__ __forceinline__ void grid_barrier(int id) {
    __syncthreads();
    if (threadIdx.x == 0) {
        __threadfence();
        atomicAdd(&g_bar[id], 1u);
        volatile unsigned* p = &g_bar[id];
        while (*p < NCTA) __nanosleep(16);
        __threadfence();
    }
    __syncthreads();
}

// ---------------------------------------------------------------------------
// Gram partial over the CTA's 64-row SMEM chunk. 2 groups of 128 threads;
// group g covers rows [g*32, g*32+32), thread tile 2 rows x 4 cols of the
// 32x32 output. Combine (fixed order) then write TRANSPOSED partial.
// ---------------------------------------------------------------------------
__device__ __forceinline__ void gram_phase(const float2* __restrict__ chunk,
                                           float* __restrict__ buf, int blk) {
    const int tid = threadIdx.x;
    const int g  = tid >> 7;        // 0..1
    const int t  = tid & 127;
    const int i0 = (t & 15) * 2;
    const int j0 = (t >> 4) * 4;
    const int r0 = g * 32;

    float2 acc[2][4];
#pragma unroll
    for (int p = 0; p < 2; ++p)
#pragma unroll
        for (int q = 0; q < 4; ++q) acc[p][q] = make_float2(0.f, 0.f);

#pragma unroll 8
    for (int r = 0; r < 32; ++r) {
        const float2* rowc = &chunk[(r0 + r) * R_COLS];
        float4 av  = *reinterpret_cast<const float4*>(rowc + i0);
        float4 bv0 = *reinterpret_cast<const float4*>(rowc + j0);
        float4 bv1 = *reinterpret_cast<const float4*>(rowc + j0 + 2);
        float2 a[2] = { {av.x, av.y}, {av.z, av.w} };
        float2 b[4] = { {bv0.x, bv0.y}, {bv0.z, bv0.w}, {bv1.x, bv1.y}, {bv1.z, bv1.w} };
#pragma unroll
        for (int p = 0; p < 2; ++p)
#pragma unroll
            for (int q = 0; q < 4; ++q) {
                acc[p][q].x = fmaf(a[p].x, b[q].x, acc[p][q].x);
                acc[p][q].x = fmaf(a[p].y, b[q].y, acc[p][q].x);
                acc[p][q].y = fmaf(a[p].x, b[q].y, acc[p][q].y);
                acc[p][q].y = fmaf(-a[p].y, b[q].x, acc[p][q].y);
            }
    }
    __syncthreads();

    if (g == 1) {                       // group 1 stores its partial
#pragma unroll
        for (int p = 0; p < 2; ++p)
#pragma unroll
            for (int q = 0; q < 4; ++q) {
                int e = ((i0 + p) * R_COLS + (j0 + q)) * 2;
                buf[e] = acc[p][q].x; buf[e + 1] = acc[p][q].y;
            }
    }
    __syncthreads();
    if (g == 0) {                       // group 0 adds and writes transposed
#pragma unroll
        for (int p = 0; p < 2; ++p)
#pragma unroll
            for (int q = 0; q < 4; ++q) {
                int e = ((i0 + p) * R_COLS + (j0 + q)) * 2;
                g_part[(size_t)e * NCTA + blk]       = acc[p][q].x + buf[e];
                g_part[(size_t)(e + 1) * NCTA + blk] = acc[p][q].y + buf[e + 1];
            }
    }
}

// ---------------------------------------------------------------------------
// Reduce: element e = blk*8 + warp. 32 lanes: each lane sums 8 consecutive
// partials (2 coalesced float4 loads), then 5-level shuffle tree. Fixed order.
// ---------------------------------------------------------------------------
__device__ __forceinline__ void reduce_phase(int blk) {
    const int w = threadIdx.x >> 5;     // 0..7
    const int l = threadIdx.x & 31;
    const int e = blk * 8 + w;
    const float4* base = reinterpret_cast<const float4*>(&g_part[(size_t)e * NCTA]);
    float4 v0 = __ldcg(&base[2 * l]);
    float4 v1 = __ldcg(&base[2 * l + 1]);
    float s = ((v0.x + v0.y) + (v0.z + v0.w)) + ((v1.x + v1.y) + (v1.z + v1.w));
    s += __shfl_down_sync(0xffffffffu, s, 16);
    s += __shfl_down_sync(0xffffffffu, s, 8);
    s += __shfl_down_sync(0xffffffffu, s, 4);
    s += __shfl_down_sync(0xffffffffu, s, 2);
    s += __shfl_down_sync(0xffffffffu, s, 1);
    if (l == 0) reinterpret_cast<float*>(g_S)[e] = s;
}

// ---------------------------------------------------------------------------
// Per-CTA (redundant) complex Cholesky of g_S + column-parallel trisolve.
// Warp 0 only. W = R^{-1} (exact upper triangular) -> smem wbuf.
// ---------------------------------------------------------------------------
__device__ __forceinline__ void cholinv_phase(float2* __restrict__ wbuf) {
    const unsigned FULL = 0xffffffffu;
    const int r = threadIdx.x;

    float2 row[R_COLS];
#pragma unroll
    for (int c = 0; c < R_COLS; ++c) row[c] = __ldcg(&g_S[r * R_COLS + c]);

#pragma unroll
    for (int k = 0; k < R_COLS; ++k) {
        float dkk  = __shfl_sync(FULL, row[k].x, k);
        float invs = rsqrtf(dkk);
        float2 l;
        l.x = row[k].x * invs;
        l.y = row[k].y * invs;
        row[k] = l;
#pragma unroll
        for (int j = k + 1; j < R_COLS; ++j) {
            float lx = __shfl_sync(FULL, l.x, j);
            float ly = __shfl_sync(FULL, l.y, j);
            row[j].x -= l.x * lx + l.y * ly;
            row[j].y -= l.y * lx - l.x * ly;
        }
    }

    float2 (*L)[R_COLS] = reinterpret_cast<float2(*)[R_COLS]>(wbuf);
#pragma unroll
    for (int k = 0; k < R_COLS; ++k) L[r][k] = row[k];
    __syncwarp();

    const int c = r;
    float2 x[R_COLS];
#pragma unroll
    for (int rr = 0; rr < R_COLS; ++rr) {
        float2 s = (rr == c) ? make_float2(1.f, 0.f) : make_float2(0.f, 0.f);
#pragma unroll
        for (int k = 0; k < rr; ++k) {
            float2 lv = L[rr][k];
            s.x -= lv.x * x[k].x - lv.y * x[k].y;
            s.y -= lv.x * x[k].y + lv.y * x[k].x;
        }
        float invd = 1.0f / L[rr][rr].x;
        x[rr] = make_float2(s.x * invd, s.y * invd);
    }
    __syncwarp();

#pragma unroll
    for (int j = 0; j < R_COLS; ++j)
        wbuf[c * R_COLS + j] = make_float2(x[j].x, -x[j].y);
}

// ---------------------------------------------------------------------------
__global__ __launch_bounds__(TPB, 2) void fused_cholqr1(const float2* __restrict__ A,
                                                        float2* __restrict__ Out) {
    __shared__ float2 chunk[CHUNK * R_COLS];   // 16 KB resident rows
    __shared__ float  scratch[2048];           // 8 KB gram buf / L / W

    const int tid = threadIdx.x;
    const int blk = blockIdx.x;

    // Stage chunk (only read of A): 1024 float4 over 256 threads = 4 iters.
    {
        const float4* src = reinterpret_cast<const float4*>(A + (size_t)blk * CHUNK * R_COLS);
        float4* dst = reinterpret_cast<float4*>(chunk);
#pragma unroll
        for (int i = 0; i < 4; ++i) dst[tid + TPB * i] = src[tid + TPB * i];
    }
    __syncthreads();

    float2* W = reinterpret_cast<float2*>(scratch);

    gram_phase(chunk, scratch, blk);
    grid_barrier(0);
    reduce_phase(blk);
    grid_barrier(1);

    // Prefetch apply's row registers while warp 0 runs cholinv.
    const int row = tid >> 2;       // 0..63
    const int c0  = tid & 3;
    float2 a[R_COLS];
    {
        const float4* rp = reinterpret_cast<const float4*>(&chunk[row * R_COLS]);
#pragma unroll
        for (int i = 0; i < 16; ++i) {
            float4 v = rp[i];
            a[2 * i]     = make_float2(v.x, v.y);
            a[2 * i + 1] = make_float2(v.z, v.w);
        }
    }

    if (tid < 32) cholinv_phase(W);
    __syncthreads();                // W ready; all chunk reads done

    // Apply: row' = row * W (upper tri). 4 threads/row, stride-4 columns.
    float2 res[8];
#pragma unroll
    for (int jj = 0; jj < 8; ++jj) {
        const int j = 4 * jj + c0;
        float2 s = make_float2(0.f, 0.f);
#pragma unroll
        for (int i = 0; i < R_COLS; ++i) {
            if (i <= 4 * jj + 3) {
                if (i <= j) {
                    float2 w = W[i * R_COLS + j];
                    s.x = fmaf(a[i].x, w.x, s.x);
                    s.x = fmaf(-a[i].y, w.y, s.x);
                    s.y = fmaf(a[i].x, w.y, s.y);
                    s.y = fmaf(a[i].y, w.x, s.y);
                }
            }
        }
        res[jj] = s;
    }
#pragma unroll
    for (int jj = 0; jj < 8; ++jj)
        chunk[row * R_COLS + 4 * jj + c0] = res[jj];
    __syncthreads();

    // Coalesced float4 copy-out: 1024 float4 over 256 threads = 4 iters.
    {
        const float4* src = reinterpret_cast<const float4*>(chunk);
        float4* dst = reinterpret_cast<float4*>(Out + (size_t)blk * CHUNK * R_COLS);
#pragma unroll
        for (int i = 0; i < 4; ++i) dst[tid + TPB * i] = src[tid + TPB * i];
    }
}

// ---------------------------------------------------------------------------
extern "C" void kernel_launch(void* const* d_in, const int* in_sizes, int n_in,
                              void* d_out, int out_size) {
    (void)in_sizes; (void)n_in; (void)out_size;
    const float2* A = reinterpret_cast<const float2*>(d_in[0]);
    float2* Out = reinterpret_cast<float2*>(d_out);

    void* barp = nullptr;
    cudaGetSymbolAddress(&barp, g_bar);
    cudaMemsetAsync(barp, 0, sizeof(unsigned) * 2);

    fused_cholqr1<<<NCTA, TPB>>>(A, Out);
}

// round 9
// speedup vs baseline: 1.0906x; 1.0906x over previous
#include <cuda_runtime.h>

// StrictOrthogonal via CholeskyQR1, persistent kernel.
// 128 CTAs x 512 threads, all co-resident -> grid barrier safe.
// Phases: [stage+gram] bar [reduce] bar [cholinv -> apply -> direct store].
// R9: spill-free cholinv (no a[] live in warp0), k-outer ILP trisolve,
// transposed L + col-major W in SMEM, apply writes straight to Out.

#define M_ROWS 16384
#define R_COLS 32
#define CHUNK  128
#define NCTA   128
#define TPB    512

__device__ float    g_part[2048 * NCTA];   // transposed partials (1 MB)
__device__ float2   g_S[R_COLS * R_COLS];  // reduced Gram
__device__ unsigned g_bar[2];              // barrier counters (memset per launch)

// ---------------------------------------------------------------------------
__device__ __forceinline__ void grid_barrier(int id) {
    __syncthreads();
    if (threadIdx.x == 0) {
        __threadfence();
        atomicAdd(&g_bar[id], 1u);
        volatile unsigned* p = &g_bar[id];
        while (*p < NCTA) __nanosleep(32);
        __threadfence();
    }
    __syncthreads();
}

// ---------------------------------------------------------------------------
// Gram partial: 4 groups of 128 threads, group g covers rows [g*32,g*32+32),
// thread tile 2x4 of the 32x32 output. Groups 1-3 park partials in smem;
// group 0 combines (fixed order) and writes TRANSPOSED to g_part[e][blk].
// ---------------------------------------------------------------------------
__device__ __forceinline__ void gram_phase(const float2* __restrict__ chunk,
                                           float* __restrict__ sc, int blk) {
    const int tid = threadIdx.x;
    const int g  = tid >> 7;        // 0..3
    const int t  = tid & 127;
    const int i0 = (t & 15) * 2;
    const int j0 = (t >> 4) * 4;
    const int r0 = g * 32;

    float2 acc[2][4];
#pragma unroll
    for (int p = 0; p < 2; ++p)
#pragma unroll
        for (int q = 0; q < 4; ++q) acc[p][q] = make_float2(0.f, 0.f);

#pragma unroll 8
    for (int r = 0; r < 32; ++r) {
        const float2* rowc = &chunk[(r0 + r) * R_COLS];
        float4 av  = *reinterpret_cast<const float4*>(rowc + i0);
        float4 bv0 = *reinterpret_cast<const float4*>(rowc + j0);
        float4 bv1 = *reinterpret_cast<const float4*>(rowc + j0 + 2);
        float2 a[2] = { {av.x, av.y}, {av.z, av.w} };
        float2 b[4] = { {bv0.x, bv0.y}, {bv0.z, bv0.w}, {bv1.x, bv1.y}, {bv1.z, bv1.w} };
#pragma unroll
        for (int p = 0; p < 2; ++p)
#pragma unroll
            for (int q = 0; q < 4; ++q) {
                acc[p][q].x = fmaf(a[p].x, b[q].x, acc[p][q].x);
                acc[p][q].x = fmaf(a[p].y, b[q].y, acc[p][q].x);
                acc[p][q].y = fmaf(a[p].x, b[q].y, acc[p][q].y);
                acc[p][q].y = fmaf(-a[p].y, b[q].x, acc[p][q].y);
            }
    }
    __syncthreads();

    if (g != 0) {
#pragma unroll
        for (int p = 0; p < 2; ++p)
#pragma unroll
            for (int q = 0; q < 4; ++q) {
                int e = ((i0 + p) * R_COLS + (j0 + q)) * 2;
                sc[(g - 1) * 2048 + e]     = acc[p][q].x;
                sc[(g - 1) * 2048 + e + 1] = acc[p][q].y;
            }
    }
    __syncthreads();
    if (g == 0) {
#pragma unroll
        for (int p = 0; p < 2; ++p)
#pragma unroll
            for (int q = 0; q < 4; ++q) {
                int e = ((i0 + p) * R_COLS + (j0 + q)) * 2;
                float sx = ((acc[p][q].x + sc[e]) + sc[2048 + e]) + sc[4096 + e];
                float sy = ((acc[p][q].y + sc[e + 1]) + sc[2048 + e + 1]) + sc[4096 + e + 1];
                g_part[(e)     * NCTA + blk] = sx;
                g_part[(e + 1) * NCTA + blk] = sy;
            }
    }
}

// ---------------------------------------------------------------------------
// Reduce: element e = blk*16 + warp (16 warps). Lane l: one coalesced float4
// (partials 4l..4l+3), then 5-level shuffle tree. Fixed order -> deterministic.
// ---------------------------------------------------------------------------
__device__ __forceinline__ void reduce_phase(int blk) {
    const int w = threadIdx.x >> 5;     // 0..15
    const int l = threadIdx.x & 31;
    const int e = blk * 16 + w;
    float4 v = __ldcg(reinterpret_cast<const float4*>(&g_part[(size_t)e * NCTA]) + l);
    float s = (v.x + v.y) + (v.z + v.w);
    s += __shfl_down_sync(0xffffffffu, s, 16);
    s += __shfl_down_sync(0xffffffffu, s, 8);
    s += __shfl_down_sync(0xffffffffu, s, 4);
    s += __shfl_down_sync(0xffffffffu, s, 2);
    s += __shfl_down_sync(0xffffffffu, s, 1);
    if (l == 0) reinterpret_cast<float*>(g_S)[e] = s;
}

// ---------------------------------------------------------------------------
// Warp 0: complex Cholesky of g_S (lane r = row r), store L TRANSPOSED in
// smem (LT[k][r], conflict-free), precompute diag reciprocals, then k-outer
// ILP trisolve (lane c = column c of L^{-1}); write W = R^{-1} col-major:
// Wcm[j*32 + i] = W[i][j]. Rows j<c produce exact zeros.
// ---------------------------------------------------------------------------
__device__ __forceinline__ void cholinv_phase(float2* __restrict__ LT,
                                              float2* __restrict__ Wcm,
                                              float* __restrict__ sinvd) {
    const unsigned FULL = 0xffffffffu;
    const int r = threadIdx.x;

    float2 row[R_COLS];
#pragma unroll
    for (int c = 0; c < R_COLS; ++c) row[c] = __ldcg(&g_S[r * R_COLS + c]);

#pragma unroll
    for (int k = 0; k < R_COLS; ++k) {
        float dkk  = __shfl_sync(FULL, row[k].x, k);
        float invs = rsqrtf(dkk);
        float2 l;
        l.x = row[k].x * invs;
        l.y = row[k].y * invs;
        row[k] = l;
#pragma unroll
        for (int j = k + 1; j < R_COLS; ++j) {
            float lx = __shfl_sync(FULL, l.x, j);
            float ly = __shfl_sync(FULL, l.y, j);
            row[j].x -= l.x * lx + l.y * ly;
            row[j].y -= l.y * lx - l.x * ly;
        }
    }

    // Store L transposed: LT[k][r] = L[r][k] for k <= r (lower triangle).
#pragma unroll
    for (int k = 0; k < R_COLS; ++k)
        if (k <= r) LT[k * R_COLS + r] = row[k];
    __syncwarp();
    sinvd[r] = 1.0f / LT[r * R_COLS + r].x;   // real positive diagonal
    __syncwarp();

    // Solve L x = e_c, k-outer (ILP): s[j]=0 for j<c stays exactly 0.
    float2 s[R_COLS];
#pragma unroll
    for (int j = 0; j < R_COLS; ++j)
        s[j] = (j == r) ? make_float2(1.f, 0.f) : make_float2(0.f, 0.f);

#pragma unroll
    for (int k = 0; k < R_COLS; ++k) {
        float dk = sinvd[k];
        s[k].x *= dk;
        s[k].y *= dk;
#pragma unroll
        for (int j = k + 1; j < R_COLS; ++j) {
            float2 lv = LT[k * R_COLS + j];       // broadcast LDS
            s[j].x -= lv.x * s[k].x - lv.y * s[k].y;
            s[j].y -= lv.x * s[k].y + lv.y * s[k].x;
        }
    }

    // W[c][j] = conj(x[j]) -> col-major Wcm[j*32 + c] (conflict-free stores).
#pragma unroll
    for (int j = 0; j < R_COLS; ++j)
        Wcm[j * R_COLS + r] = make_float2(s[j].x, -s[j].y);
}

// ---------------------------------------------------------------------------
__global__ __launch_bounds__(TPB, 1) void fused_cholqr1(const float2* __restrict__ A,
                                                        float2* __restrict__ Out) {
    __shared__ float2 chunk[CHUNK * R_COLS];   // 32 KB resident rows
    __shared__ float  sc[3 * 2048];            // 24 KB: gram bufs / LT / Wcm
    __shared__ float  sinvd[R_COLS];

    const int tid = threadIdx.x;
    const int blk = blockIdx.x;

    // Stage chunk (only read of A): 2048 float4 over 512 threads = 4 iters.
    {
        const float4* src = reinterpret_cast<const float4*>(A + (size_t)blk * CHUNK * R_COLS);
        float4* dst = reinterpret_cast<float4*>(chunk);
#pragma unroll
        for (int i = 0; i < 4; ++i) dst[tid + TPB * i] = src[tid + TPB * i];
    }
    __syncthreads();

    gram_phase(chunk, sc, blk);
    grid_barrier(0);
    reduce_phase(blk);
    grid_barrier(1);

    float2* LT  = reinterpret_cast<float2*>(sc);          // 8 KB
    float2* Wcm = reinterpret_cast<float2*>(sc + 2048);   // 8 KB

    if (tid < 32) cholinv_phase(LT, Wcm, sinvd);
    __syncthreads();                // Wcm ready

    // Apply + direct store: 4 threads per row, stride-4 columns.
    const int row = tid >> 2;       // 0..127
    const int c0  = tid & 3;

    float2 a[R_COLS];
    {
        const float4* rp = reinterpret_cast<const float4*>(&chunk[row * R_COLS]);
#pragma unroll
        for (int i = 0; i < 16; ++i) {
            float4 v = rp[i];
            a[2 * i]     = make_float2(v.x, v.y);
            a[2 * i + 1] = make_float2(v.z, v.w);
        }
    }

    float2* outr = Out + ((size_t)blk * CHUNK + row) * R_COLS;
#pragma unroll
    for (int jj = 0; jj < 8; ++jj) {
        const int j = 4 * jj + c0;
        const float2* wj = &Wcm[j * R_COLS];
        float2 s = make_float2(0.f, 0.f);
#pragma unroll
        for (int i = 0; i < R_COLS; ++i) {
            if (i <= 4 * jj + 3) {          // compile-time prune of tail
                if (i <= j) {               // runtime triangular guard
                    float2 w = wj[i];
                    s.x = fmaf(a[i].x, w.x, s.x);
                    s.x = fmaf(-a[i].y, w.y, s.x);
                    s.y = fmaf(a[i].x, w.y, s.y);
                    s.y = fmaf(a[i].y, w.x, s.y);
                }
            }
        }
        outr[j] = s;                        // direct global store
    }
}

// ---------------------------------------------------------------------------
extern "C" void kernel_launch(void* const* d_in, const int* in_sizes, int n_in,
                              void* d_out, int out_size) {
    (void)in_sizes; (void)n_in; (void)out_size;
    const float2* A = reinterpret_cast<const float2*>(d_in[0]);
    float2* Out = reinterpret_cast<float2*>(d_out);

    void* barp = nullptr;
    cudaGetSymbolAddress(&barp, g_bar);
    cudaMemsetAsync(barp, 0, sizeof(unsigned) * 2);

    fused_cholqr1<<<NCTA, TPB>>>(A, Out);
}